// round 15
// baseline (speedup 1.0000x reference)
#include <cuda_runtime.h>
#include <cstdint>

#define Bq 128
#define Tq 512
#define TAGq 256
#define START_TAG 254
#define STOP_TAG 255
#define NTHREADS 256       // one thread per tag; full 256-j reduction per thread
#define RJ4 48             // trans float4 per thread in registers (j = 0..191)
#define TJ4 16             // tile f4 per row (j = 192..255)
#define TSTRIDE4 17        // tile row stride in f4 (68 floats == 4 mod 32 banks)
#define CROWS 224          // transT rows cached in backward SMEM

// Scratch (allocation-free rule: static __device__ globals)
__device__ float g_hist[(size_t)Bq * Tq * TAGq];   // partition history, 64 MB
__device__ float g_transT[TAGq * TAGq];            // transposed transitions

__device__ __forceinline__ float2 fadd2_(float2 a, float2 b) {
    float2 o;
    asm("{\n\t"
        ".reg .b64 ra, rb, rc;\n\t"
        "mov.b64 ra, {%2,%3};\n\t"
        "mov.b64 rb, {%4,%5};\n\t"
        "add.rn.f32x2 rc, ra, rb;\n\t"
        "mov.b64 {%0,%1}, rc;\n\t"
        "}"
        : "=f"(o.x), "=f"(o.y)
        : "f"(a.x), "f"(a.y), "f"(b.x), "f"(b.y));
    return o;
}

__device__ __forceinline__ float neg_inf() { return __int_as_float(0xff800000u); }

// Strictly order-preserving float -> u32 key (finite values, no NaN here).
__device__ __forceinline__ unsigned okey(float f) {
    unsigned u = __float_as_uint(f);
    return (u & 0x80000000u) ? ~u : (u | 0x80000000u);
}
__device__ __forceinline__ float okey_dec(unsigned k) {
    unsigned u = (k & 0x80000000u) ? (k & 0x7fffffffu) : ~k;
    return __uint_as_float(u);
}

// ---------------------------------------------------------------------------
// transT[t2][j] = trans[j][t2]
__global__ void transpose_kernel(const float* __restrict__ trans) {
    int j  = blockIdx.x;
    int t2 = threadIdx.x;
    g_transT[t2 * TAGq + j] = trans[j * TAGq + t2];
}

// No-op launch: shifts the ncu -s/-c capture window phase so the profile has
// a chance to land on forward/backward instead of transpose. ~2us.
__global__ void phase_kernel() {}

// ---------------------------------------------------------------------------
// Forward Viterbi: one CTA per batch, 256 threads, ONE thread per tag, ONE
// barrier per step. Thread reduces over ALL 256 j:
//   trans[tag][0..192)    -> 48 float4 REGISTERS (loop-invariant)
//   trans[tag][192..256)  -> SMEM tile row (stride 17 f4, conflict-free)
//   part[]                -> SMEM broadcast
__global__ __launch_bounds__(NTHREADS, 1)
void forward_kernel(const float* __restrict__ feats,
                    const float* __restrict__ trans) {
    extern __shared__ float smem_f[];
    float* tile = smem_f;                          // [256][68] floats
    float* bufA = smem_f + TAGq * TSTRIDE4 * 4;    // 256
    float* bufB = bufA + TAGq;                     // 256

    const int b   = blockIdx.x;
    const int tag = threadIdx.x;

    // Stage tile: tile[r] f4 [0,16) = transT[r] f4 [48,64)  (j = 192..255)
    for (int idx = tag; idx < TAGq * TJ4; idx += NTHREADS) {
        int r = idx / TJ4, c4 = idx % TJ4;
        ((float4*)tile)[r * TSTRIDE4 + c4] =
            ((const float4*)g_transT)[r * 64 + 48 + c4];
    }

    // Register-resident trans slice: transT[tag][0 .. 192)
    float4 tr4[RJ4];
    {
        const float4* src = (const float4*)(g_transT + (size_t)tag * TAGq);
        #pragma unroll
        for (int k = 0; k < RJ4; ++k) tr4[k] = src[k];
    }

    const float* febase = feats + (size_t)b * Tq * TAGq;
    float*       hbase  = g_hist + (size_t)b * Tq * TAGq;

    // part0 = feats[b,0,:] + trans[START,:]
    {
        float p0 = febase[tag] + trans[START_TAG * TAGq + tag];
        bufA[tag] = p0;
        hbase[tag] = p0;
    }

    // prefetch emission for t = 1
    float e = __ldcs(febase + (size_t)TAGq + tag);
    __syncthreads();

    const float4* trow_s = (const float4*)tile + tag * TSTRIDE4;

    float* cur = bufA;
    float* nxt = bufB;

    for (int t = 1; t < Tq; ++t) {
        // prefetch next step's emission (one full step of latency slack)
        const int tn = (t + 1 < Tq) ? (t + 1) : t;
        float e_nxt = __ldcs(febase + (size_t)tn * TAGq + tag);

        const float2 e2 = make_float2(e, e);
        const float4* p4 = (const float4*)cur;    // warp-broadcast

        float a0 = neg_inf(), a1 = a0, a2 = a0, a3 = a0;
        float a4 = a0, a5 = a0, a6 = a0, a7 = a0;

        // j in [0, 192): trans from registers
        #pragma unroll
        for (int k = 0; k < RJ4; ++k) {
            float4 pa = p4[k];
            float4 ta = tr4[k];
            float2 s;
            s = fadd2_(fadd2_(e2, make_float2(ta.x, ta.y)), make_float2(pa.x, pa.y));
            a0 = fmaxf(a0, s.x); a1 = fmaxf(a1, s.y);
            s = fadd2_(fadd2_(e2, make_float2(ta.z, ta.w)), make_float2(pa.z, pa.w));
            a2 = fmaxf(a2, s.x); a3 = fmaxf(a3, s.y);
        }
        // j in [192, 256): trans from SMEM tile
        #pragma unroll
        for (int k = 0; k < TJ4; ++k) {
            float4 pb = p4[RJ4 + k];
            float4 tb = trow_s[k];
            float2 s;
            s = fadd2_(fadd2_(e2, make_float2(tb.x, tb.y)), make_float2(pb.x, pb.y));
            a4 = fmaxf(a4, s.x); a5 = fmaxf(a5, s.y);
            s = fadd2_(fadd2_(e2, make_float2(tb.z, tb.w)), make_float2(pb.z, pb.w));
            a6 = fmaxf(a6, s.x); a7 = fmaxf(a7, s.y);
        }
        float m = fmaxf(fmaxf(fmaxf(a0, a1), fmaxf(a2, a3)),
                        fmaxf(fmaxf(a4, a5), fmaxf(a6, a7)));

        nxt[tag] = m;
        hbase[(size_t)t * TAGq + tag] = m;
        __syncthreads();

        float* tp = cur; cur = nxt; nxt = tp;
        e = e_nxt;
    }
}

// ---------------------------------------------------------------------------
// Warp argmax over 256 values with jnp.argmax first-index semantics.
__device__ __forceinline__ int warp_argmax256(float xv, int xi, float* vmax_out) {
    unsigned kk   = okey(xv);
    unsigned kmax = __reduce_max_sync(0xffffffffu, kk);
    unsigned cand = (kk == kmax) ? (unsigned)xi : 0x7fffffffu;
    unsigned imin = __reduce_min_sync(0xffffffffu, cand);
    if (vmax_out) *vmax_out = okey_dec(kmax);
    return (int)imin;
}

// Backward (R11 structure, measured): one CTA of 256 threads per batch.
// Warps 0..7 stage transT rows [0, CROWS) into SMEM; warp 0 runs the chain.
__global__ __launch_bounds__(256, 1)
void backward_kernel(const float* __restrict__ feats,
                     const int*   __restrict__ mask,
                     float*       __restrict__ out) {
    extern __shared__ float cache[];   // [CROWS][256]

    const int b = blockIdx.x;
    const int tid = threadIdx.x;

    for (int idx = tid; idx < CROWS * 64; idx += 256)
        ((float4*)cache)[idx] = ((const float4*)g_transT)[idx];
    __syncthreads();

    if (tid >= 32) return;
    const int lane = tid;

    int len = 0;
    for (int i = lane; i < Tq; i += 32) len += mask[b * Tq + i];
    #pragma unroll
    for (int o = 16; o; o >>= 1) len += __shfl_down_sync(0xffffffffu, len, o);
    len = __shfl_sync(0xffffffffu, len, 0);
    const int last = len - 1;

    const float* hb = g_hist + (size_t)b * Tq * TAGq;
    const int j0 = lane * 4;
    const int j1 = 128 + lane * 4;

    int ptr;
    {
        const float4* lp4 = (const float4*)(hb + (size_t)last * TAGq);
        const float4* tc4 = (const float4*)(g_transT + STOP_TAG * TAGq);
        float4 A = lp4[lane], B = lp4[lane + 32];
        float4 C = tc4[lane], D = tc4[lane + 32];
        float v[8] = {A.x + C.x, A.y + C.y, A.z + C.z, A.w + C.w,
                      B.x + D.x, B.y + D.y, B.z + D.z, B.w + D.w};
        float xv = v[0]; int xi = j0;
        #pragma unroll
        for (int k = 1; k < 4; ++k)
            if (v[k] > xv) { xv = v[k]; xi = j0 + k; }
        #pragma unroll
        for (int k = 0; k < 4; ++k)
            if (v[4 + k] > xv) { xv = v[4 + k]; xi = j1 + k; }
        float bv;
        ptr = warp_argmax256(xv, xi, &bv);
        if (lane == 0) out[b] = bv;
    }

    float* dec = out + Bq;
    if (lane == 0) dec[(size_t)b * Tq + (Tq - 1)] = (float)ptr;

    const float4* cache4 = (const float4*)cache;

    int cur = ptr;
    for (int i = Tq - 2; i >= 0; --i) {
        {
            float d0;
            const float* fr = feats + ((size_t)b * Tq + i) * TAGq + lane * 8;
            asm volatile("ld.global.nc.f32 %0, [%1];" : "=f"(d0) : "l"(fr));
            if (i >= 1) {
                float d1;
                const float* hr = hb + (size_t)(i - 1) * TAGq + lane * 8;
                asm volatile("ld.global.nc.f32 %0, [%1];" : "=f"(d1) : "l"(hr));
            }
        }

        int nv;
        if (i == last) {
            nv = ptr;
        } else if (mask[b * Tq + i + 1] == 0) {
            nv = 0;
        } else {
            const float e =
                __ldg(feats + ((size_t)b * Tq + (i + 1)) * TAGq + cur);
            const float4* h4 = (const float4*)(hb + (size_t)i * TAGq);
            float4 H0 = h4[lane], H1 = h4[lane + 32];
            float4 T0, T1;
            if (cur < CROWS) {
                T0 = cache4[cur * 64 + lane];
                T1 = cache4[cur * 64 + 32 + lane];
            } else {
                const float4* t4 = (const float4*)(g_transT + (size_t)cur * TAGq);
                T0 = t4[lane];
                T1 = t4[lane + 32];
            }
            float v[8] = {(e + T0.x) + H0.x, (e + T0.y) + H0.y,
                          (e + T0.z) + H0.z, (e + T0.w) + H0.w,
                          (e + T1.x) + H1.x, (e + T1.y) + H1.y,
                          (e + T1.z) + H1.z, (e + T1.w) + H1.w};
            float xv = v[0]; int xi = j0;
            #pragma unroll
            for (int k = 1; k < 4; ++k)
                if (v[k] > xv) { xv = v[k]; xi = j0 + k; }
            #pragma unroll
            for (int k = 0; k < 4; ++k)
                if (v[4 + k] > xv) { xv = v[4 + k]; xi = j1 + k; }
            nv = warp_argmax256(xv, xi, nullptr);
        }
        cur = nv;
        if (lane == 0) dec[(size_t)b * Tq + i] = (float)cur;
    }
}

// ---------------------------------------------------------------------------
extern "C" void kernel_launch(void* const* d_in, const int* in_sizes, int n_in,
                              void* d_out, int out_size) {
    const float* feats = (const float*)d_in[0];   // (128,512,256) f32
    const int*   mask  = (const int*)d_in[1];     // (128,512) i32
    const float* trans = (const float*)d_in[2];   // (256,256) f32
    float* out = (float*)d_out;                   // [128 path_score | 128*512 decode]

    transpose_kernel<<<TAGq, TAGq>>>(trans);

    const size_t smem_f =
        (size_t)(TAGq * TSTRIDE4 * 4 + 2 * TAGq) * sizeof(float); // 71680 B
    cudaFuncSetAttribute(forward_kernel,
                         cudaFuncAttributeMaxDynamicSharedMemorySize, (int)smem_f);
    forward_kernel<<<Bq, NTHREADS, smem_f>>>(feats, trans);

    const size_t smem_b = (size_t)CROWS * TAGq * sizeof(float);   // 229376 B
    cudaFuncSetAttribute(backward_kernel,
                         cudaFuncAttributeMaxDynamicSharedMemorySize, (int)smem_b);
    backward_kernel<<<Bq, 256, smem_b>>>(feats, mask, out);

    phase_kernel<<<1, 32>>>();   // shift ncu capture window phase
}

// round 16
// speedup vs baseline: 1.1392x; 1.1392x over previous
#include <cuda_runtime.h>
#include <cstdint>

#define Bq 128
#define Tq 512
#define TAGq 256
#define START_TAG 254
#define STOP_TAG 255
#define NTHREADS 256       // one thread per tag; full 256-j reduction per thread
#define RJ 160             // trans floats per thread held in registers (40 f4)
#define TJ4 24             // tile f4 per row ((256-RJ)/4)
#define TSTRIDE4 25        // tile row stride in f4 (100 floats == 4 mod 32 banks)
#define CROWS 224          // transT rows cached in backward SMEM

// Scratch (allocation-free rule: static __device__ globals)
__device__ float g_hist[(size_t)Bq * Tq * TAGq];   // partition history, 64 MB
__device__ float g_transT[TAGq * TAGq];            // transposed transitions

__device__ __forceinline__ float2 fadd2_(float2 a, float2 b) {
    float2 o;
    asm("{\n\t"
        ".reg .b64 ra, rb, rc;\n\t"
        "mov.b64 ra, {%2,%3};\n\t"
        "mov.b64 rb, {%4,%5};\n\t"
        "add.rn.f32x2 rc, ra, rb;\n\t"
        "mov.b64 {%0,%1}, rc;\n\t"
        "}"
        : "=f"(o.x), "=f"(o.y)
        : "f"(a.x), "f"(a.y), "f"(b.x), "f"(b.y));
    return o;
}

__device__ __forceinline__ float neg_inf() { return __int_as_float(0xff800000u); }

// Strictly order-preserving float -> u32 key (finite values, no NaN here).
__device__ __forceinline__ unsigned okey(float f) {
    unsigned u = __float_as_uint(f);
    return (u & 0x80000000u) ? ~u : (u | 0x80000000u);
}
__device__ __forceinline__ float okey_dec(unsigned k) {
    unsigned u = (k & 0x80000000u) ? (k & 0x7fffffffu) : ~k;
    return __uint_as_float(u);
}

// ---------------------------------------------------------------------------
// transT[t2][j] = trans[j][t2]
__global__ void transpose_kernel(const float* __restrict__ trans) {
    int j  = blockIdx.x;
    int t2 = threadIdx.x;
    g_transT[t2 * TAGq + j] = trans[j * TAGq + t2];
}

// Dummy launches: position forward_kernel as the 4th launch so the ncu
// capture window (observed to land on launch #4) profiles the hot kernel.
__global__ void dummy_kernel() {}

// ---------------------------------------------------------------------------
// Forward Viterbi (R13 structure, measured 820.7us): one CTA per batch, 256
// threads, ONE thread per tag, ONE barrier per step. Thread reduces over ALL
// 256 j:
//   trans[tag][0..160)    -> 40 float4 REGISTERS (loop-invariant)
//   trans[tag][160..256)  -> SMEM tile row (stride 25 f4, conflict-free)
//   part[]                -> SMEM broadcast
__global__ __launch_bounds__(NTHREADS, 1)
void forward_kernel(const float* __restrict__ feats,
                    const float* __restrict__ trans) {
    extern __shared__ float smem_f[];
    float* tile = smem_f;                          // [256][100] floats
    float* bufA = smem_f + TAGq * TSTRIDE4 * 4;    // 256
    float* bufB = bufA + TAGq;                     // 256

    const int b   = blockIdx.x;
    const int tag = threadIdx.x;

    // Stage tile: tile[r] f4 [0,24) = transT[r] f4 [40,64)  (j = 160..255)
    for (int idx = tag; idx < TAGq * TJ4; idx += NTHREADS) {
        int r = idx / TJ4, c4 = idx % TJ4;
        ((float4*)tile)[r * TSTRIDE4 + c4] =
            ((const float4*)g_transT)[r * 64 + 40 + c4];
    }

    // Register-resident trans slice: transT[tag][0 .. RJ)
    float4 tr4[40];
    {
        const float4* src = (const float4*)(g_transT + (size_t)tag * TAGq);
        #pragma unroll
        for (int k = 0; k < 40; ++k) tr4[k] = src[k];
    }

    const float* febase = feats + (size_t)b * Tq * TAGq;
    float*       hbase  = g_hist + (size_t)b * Tq * TAGq;

    // part0 = feats[b,0,:] + trans[START,:]
    {
        float p0 = febase[tag] + trans[START_TAG * TAGq + tag];
        bufA[tag] = p0;
        hbase[tag] = p0;
    }

    // prefetch emission for t = 1
    float e = __ldcs(febase + (size_t)TAGq + tag);
    __syncthreads();

    const float4* trow_s = (const float4*)tile + tag * TSTRIDE4;

    float* cur = bufA;
    float* nxt = bufB;

    for (int t = 1; t < Tq; ++t) {
        // prefetch next step's emission (one full step of latency slack)
        const int tn = (t + 1 < Tq) ? (t + 1) : t;
        float e_nxt = __ldcs(febase + (size_t)tn * TAGq + tag);

        const float2 e2 = make_float2(e, e);
        const float4* p4 = (const float4*)cur;    // warp-broadcast

        float a0 = neg_inf(), a1 = a0, a2 = a0, a3 = a0;
        float a4 = a0, a5 = a0, a6 = a0, a7 = a0;

        // j in [0, RJ): trans from registers
        #pragma unroll
        for (int k = 0; k < 40; ++k) {
            float4 pa = p4[k];
            float4 ta = tr4[k];
            float2 s;
            s = fadd2_(fadd2_(e2, make_float2(ta.x, ta.y)), make_float2(pa.x, pa.y));
            a0 = fmaxf(a0, s.x); a1 = fmaxf(a1, s.y);
            s = fadd2_(fadd2_(e2, make_float2(ta.z, ta.w)), make_float2(pa.z, pa.w));
            a2 = fmaxf(a2, s.x); a3 = fmaxf(a3, s.y);
        }
        // j in [RJ, 256): trans from SMEM tile
        #pragma unroll
        for (int k = 0; k < 24; ++k) {
            float4 pb = p4[40 + k];
            float4 tb = trow_s[k];
            float2 s;
            s = fadd2_(fadd2_(e2, make_float2(tb.x, tb.y)), make_float2(pb.x, pb.y));
            a4 = fmaxf(a4, s.x); a5 = fmaxf(a5, s.y);
            s = fadd2_(fadd2_(e2, make_float2(tb.z, tb.w)), make_float2(pb.z, pb.w));
            a6 = fmaxf(a6, s.x); a7 = fmaxf(a7, s.y);
        }
        float m = fmaxf(fmaxf(fmaxf(a0, a1), fmaxf(a2, a3)),
                        fmaxf(fmaxf(a4, a5), fmaxf(a6, a7)));

        nxt[tag] = m;
        hbase[(size_t)t * TAGq + tag] = m;
        __syncthreads();

        float* tp = cur; cur = nxt; nxt = tp;
        e = e_nxt;
    }
}

// ---------------------------------------------------------------------------
// Warp argmax over 256 values with jnp.argmax first-index semantics.
__device__ __forceinline__ int warp_argmax256(float xv, int xi, float* vmax_out) {
    unsigned kk   = okey(xv);
    unsigned kmax = __reduce_max_sync(0xffffffffu, kk);
    unsigned cand = (kk == kmax) ? (unsigned)xi : 0x7fffffffu;
    unsigned imin = __reduce_min_sync(0xffffffffu, cand);
    if (vmax_out) *vmax_out = okey_dec(kmax);
    return (int)imin;
}

// Backward (R11 structure, measured): one CTA of 256 threads per batch.
// Warps 0..7 stage transT rows [0, CROWS) into SMEM; warp 0 runs the chain.
__global__ __launch_bounds__(256, 1)
void backward_kernel(const float* __restrict__ feats,
                     const int*   __restrict__ mask,
                     float*       __restrict__ out) {
    extern __shared__ float cache[];   // [CROWS][256]

    const int b = blockIdx.x;
    const int tid = threadIdx.x;

    for (int idx = tid; idx < CROWS * 64; idx += 256)
        ((float4*)cache)[idx] = ((const float4*)g_transT)[idx];
    __syncthreads();

    if (tid >= 32) return;
    const int lane = tid;

    int len = 0;
    for (int i = lane; i < Tq; i += 32) len += mask[b * Tq + i];
    #pragma unroll
    for (int o = 16; o; o >>= 1) len += __shfl_down_sync(0xffffffffu, len, o);
    len = __shfl_sync(0xffffffffu, len, 0);
    const int last = len - 1;

    const float* hb = g_hist + (size_t)b * Tq * TAGq;
    const int j0 = lane * 4;
    const int j1 = 128 + lane * 4;

    int ptr;
    {
        const float4* lp4 = (const float4*)(hb + (size_t)last * TAGq);
        const float4* tc4 = (const float4*)(g_transT + STOP_TAG * TAGq);
        float4 A = lp4[lane], B = lp4[lane + 32];
        float4 C = tc4[lane], D = tc4[lane + 32];
        float v[8] = {A.x + C.x, A.y + C.y, A.z + C.z, A.w + C.w,
                      B.x + D.x, B.y + D.y, B.z + D.z, B.w + D.w};
        float xv = v[0]; int xi = j0;
        #pragma unroll
        for (int k = 1; k < 4; ++k)
            if (v[k] > xv) { xv = v[k]; xi = j0 + k; }
        #pragma unroll
        for (int k = 0; k < 4; ++k)
            if (v[4 + k] > xv) { xv = v[4 + k]; xi = j1 + k; }
        float bv;
        ptr = warp_argmax256(xv, xi, &bv);
        if (lane == 0) out[b] = bv;
    }

    float* dec = out + Bq;
    if (lane == 0) dec[(size_t)b * Tq + (Tq - 1)] = (float)ptr;

    const float4* cache4 = (const float4*)cache;

    int cur = ptr;
    for (int i = Tq - 2; i >= 0; --i) {
        {
            float d0;
            const float* fr = feats + ((size_t)b * Tq + i) * TAGq + lane * 8;
            asm volatile("ld.global.nc.f32 %0, [%1];" : "=f"(d0) : "l"(fr));
            if (i >= 1) {
                float d1;
                const float* hr = hb + (size_t)(i - 1) * TAGq + lane * 8;
                asm volatile("ld.global.nc.f32 %0, [%1];" : "=f"(d1) : "l"(hr));
            }
        }

        int nv;
        if (i == last) {
            nv = ptr;
        } else if (mask[b * Tq + i + 1] == 0) {
            nv = 0;
        } else {
            const float e =
                __ldg(feats + ((size_t)b * Tq + (i + 1)) * TAGq + cur);
            const float4* h4 = (const float4*)(hb + (size_t)i * TAGq);
            float4 H0 = h4[lane], H1 = h4[lane + 32];
            float4 T0, T1;
            if (cur < CROWS) {
                T0 = cache4[cur * 64 + lane];
                T1 = cache4[cur * 64 + 32 + lane];
            } else {
                const float4* t4 = (const float4*)(g_transT + (size_t)cur * TAGq);
                T0 = t4[lane];
                T1 = t4[lane + 32];
            }
            float v[8] = {(e + T0.x) + H0.x, (e + T0.y) + H0.y,
                          (e + T0.z) + H0.z, (e + T0.w) + H0.w,
                          (e + T1.x) + H1.x, (e + T1.y) + H1.y,
                          (e + T1.z) + H1.z, (e + T1.w) + H1.w};
            float xv = v[0]; int xi = j0;
            #pragma unroll
            for (int k = 1; k < 4; ++k)
                if (v[k] > xv) { xv = v[k]; xi = j0 + k; }
            #pragma unroll
            for (int k = 0; k < 4; ++k)
                if (v[4 + k] > xv) { xv = v[4 + k]; xi = j1 + k; }
            nv = warp_argmax256(xv, xi, nullptr);
        }
        cur = nv;
        if (lane == 0) dec[(size_t)b * Tq + i] = (float)cur;
    }
}

// ---------------------------------------------------------------------------
extern "C" void kernel_launch(void* const* d_in, const int* in_sizes, int n_in,
                              void* d_out, int out_size) {
    const float* feats = (const float*)d_in[0];   // (128,512,256) f32
    const int*   mask  = (const int*)d_in[1];     // (128,512) i32
    const float* trans = (const float*)d_in[2];   // (256,256) f32
    float* out = (float*)d_out;                   // [128 path_score | 128*512 decode]

    transpose_kernel<<<TAGq, TAGq>>>(trans);      // launch #1
    dummy_kernel<<<1, 32>>>();                    // launch #2
    dummy_kernel<<<1, 32>>>();                    // launch #3

    const size_t smem_f =
        (size_t)(TAGq * TSTRIDE4 * 4 + 2 * TAGq) * sizeof(float); // 104448 B
    cudaFuncSetAttribute(forward_kernel,
                         cudaFuncAttributeMaxDynamicSharedMemorySize, (int)smem_f);
    forward_kernel<<<Bq, NTHREADS, smem_f>>>(feats, trans);       // launch #4 (ncu)

    const size_t smem_b = (size_t)CROWS * TAGq * sizeof(float);   // 229376 B
    cudaFuncSetAttribute(backward_kernel,
                         cudaFuncAttributeMaxDynamicSharedMemorySize, (int)smem_b);
    backward_kernel<<<Bq, 256, smem_b>>>(feats, mask, out);       // launch #5
}

// round 17
// speedup vs baseline: 1.1520x; 1.0112x over previous
#include <cuda_runtime.h>
#include <cstdint>

#define Bq 128
#define Tq 512
#define TAGq 256
#define START_TAG 254
#define STOP_TAG 255
#define NTHREADS 256       // one thread per tag; full 256-j reduction per thread
#define RJ 160             // trans floats per thread held in registers (40 f4)
#define TJ4 24             // tile f4 per row ((256-RJ)/4)
#define TSTRIDE4 25        // tile row stride in f4 (100 floats == 4 mod 32 banks)

// Scratch (allocation-free rule: static __device__ globals)
__device__ float g_hist[(size_t)Bq * Tq * TAGq];   // partition history, 64 MB
__device__ float g_transT[TAGq * TAGq];            // transposed transitions

__device__ __forceinline__ float2 fadd2_(float2 a, float2 b) {
    float2 o;
    asm("{\n\t"
        ".reg .b64 ra, rb, rc;\n\t"
        "mov.b64 ra, {%2,%3};\n\t"
        "mov.b64 rb, {%4,%5};\n\t"
        "add.rn.f32x2 rc, ra, rb;\n\t"
        "mov.b64 {%0,%1}, rc;\n\t"
        "}"
        : "=f"(o.x), "=f"(o.y)
        : "f"(a.x), "f"(a.y), "f"(b.x), "f"(b.y));
    return o;
}

__device__ __forceinline__ float neg_inf() { return __int_as_float(0xff800000u); }

// Strictly order-preserving float -> u32 key (finite values, no NaN here).
__device__ __forceinline__ unsigned okey(float f) {
    unsigned u = __float_as_uint(f);
    return (u & 0x80000000u) ? ~u : (u | 0x80000000u);
}
__device__ __forceinline__ float okey_dec(unsigned k) {
    unsigned u = (k & 0x80000000u) ? (k & 0x7fffffffu) : ~k;
    return __uint_as_float(u);
}

// Streaming (evict-first) touch: warms the line without displacing
// evict-normal data (the warmed transT) from L1.
__device__ __forceinline__ void touch_cs(const float* p) {
    float d;
    asm volatile("ld.global.cs.f32 %0, [%1];" : "=f"(d) : "l"(p));
}

// ---------------------------------------------------------------------------
// transT[t2][j] = trans[j][t2]
__global__ void transpose_kernel(const float* __restrict__ trans) {
    int j  = blockIdx.x;
    int t2 = threadIdx.x;
    g_transT[t2 * TAGq + j] = trans[j * TAGq + t2];
}

// Dummy launch: keeps the absolute-#4 ncu capture slot on backward_kernel.
__global__ void dummy_kernel() {}

// ---------------------------------------------------------------------------
// Forward Viterbi (R13 structure, measured 557us, ~84% of crossbar floor):
// one CTA per batch, 256 threads, ONE thread per tag, ONE barrier per step.
//   trans[tag][0..160)    -> 40 float4 REGISTERS (loop-invariant)
//   trans[tag][160..256)  -> SMEM tile row (stride 25 f4, conflict-free)
//   part[]                -> SMEM broadcast
__global__ __launch_bounds__(NTHREADS, 1)
void forward_kernel(const float* __restrict__ feats,
                    const float* __restrict__ trans) {
    extern __shared__ float smem_f[];
    float* tile = smem_f;                          // [256][100] floats
    float* bufA = smem_f + TAGq * TSTRIDE4 * 4;    // 256
    float* bufB = bufA + TAGq;                     // 256

    const int b   = blockIdx.x;
    const int tag = threadIdx.x;

    // Stage tile: tile[r] f4 [0,24) = transT[r] f4 [40,64)  (j = 160..255)
    for (int idx = tag; idx < TAGq * TJ4; idx += NTHREADS) {
        int r = idx / TJ4, c4 = idx % TJ4;
        ((float4*)tile)[r * TSTRIDE4 + c4] =
            ((const float4*)g_transT)[r * 64 + 40 + c4];
    }

    // Register-resident trans slice: transT[tag][0 .. RJ)
    float4 tr4[40];
    {
        const float4* src = (const float4*)(g_transT + (size_t)tag * TAGq);
        #pragma unroll
        for (int k = 0; k < 40; ++k) tr4[k] = src[k];
    }

    const float* febase = feats + (size_t)b * Tq * TAGq;
    float*       hbase  = g_hist + (size_t)b * Tq * TAGq;

    // part0 = feats[b,0,:] + trans[START,:]
    {
        float p0 = febase[tag] + trans[START_TAG * TAGq + tag];
        bufA[tag] = p0;
        hbase[tag] = p0;
    }

    // prefetch emission for t = 1
    float e = __ldcs(febase + (size_t)TAGq + tag);
    __syncthreads();

    const float4* trow_s = (const float4*)tile + tag * TSTRIDE4;

    float* cur = bufA;
    float* nxt = bufB;

    for (int t = 1; t < Tq; ++t) {
        // prefetch next step's emission (one full step of latency slack)
        const int tn = (t + 1 < Tq) ? (t + 1) : t;
        float e_nxt = __ldcs(febase + (size_t)tn * TAGq + tag);

        const float2 e2 = make_float2(e, e);
        const float4* p4 = (const float4*)cur;    // warp-broadcast

        float a0 = neg_inf(), a1 = a0, a2 = a0, a3 = a0;
        float a4 = a0, a5 = a0, a6 = a0, a7 = a0;

        // j in [0, RJ): trans from registers
        #pragma unroll
        for (int k = 0; k < 40; ++k) {
            float4 pa = p4[k];
            float4 ta = tr4[k];
            float2 s;
            s = fadd2_(fadd2_(e2, make_float2(ta.x, ta.y)), make_float2(pa.x, pa.y));
            a0 = fmaxf(a0, s.x); a1 = fmaxf(a1, s.y);
            s = fadd2_(fadd2_(e2, make_float2(ta.z, ta.w)), make_float2(pa.z, pa.w));
            a2 = fmaxf(a2, s.x); a3 = fmaxf(a3, s.y);
        }
        // j in [RJ, 256): trans from SMEM tile
        #pragma unroll
        for (int k = 0; k < 24; ++k) {
            float4 pb = p4[40 + k];
            float4 tb = trow_s[k];
            float2 s;
            s = fadd2_(fadd2_(e2, make_float2(tb.x, tb.y)), make_float2(pb.x, pb.y));
            a4 = fmaxf(a4, s.x); a5 = fmaxf(a5, s.y);
            s = fadd2_(fadd2_(e2, make_float2(tb.z, tb.w)), make_float2(pb.z, pb.w));
            a6 = fmaxf(a6, s.x); a7 = fmaxf(a7, s.y);
        }
        float m = fmaxf(fmaxf(fmaxf(a0, a1), fmaxf(a2, a3)),
                        fmaxf(fmaxf(a4, a5), fmaxf(a6, a7)));

        nxt[tag] = m;
        hbase[(size_t)t * TAGq + tag] = m;
        __syncthreads();

        float* tp = cur; cur = nxt; nxt = tp;
        e = e_nxt;
    }
}

// ---------------------------------------------------------------------------
// Warp argmax over 256 values with jnp.argmax first-index semantics.
__device__ __forceinline__ int warp_argmax256(float xv, int xi, float* vmax_out) {
    unsigned kk   = okey(xv);
    unsigned kmax = __reduce_max_sync(0xffffffffu, kk);
    unsigned cand = (kk == kmax) ? (unsigned)xi : 0x7fffffffu;
    unsigned imin = __reduce_min_sync(0xffffffffu, cand);
    if (vmax_out) *vmax_out = okey_dec(kmax);
    return (int)imin;
}

// Backward: one CTA of 256 threads per batch. NO SMEM (full 228KB L1D).
// All 8 warps first warm the entire transT (256KB) into L1 at evict-normal
// priority; warp 0 then runs the sequential backtrace. Streamed rows
// (feats/hist) are touched with ld.global.cs (evict-first) so they don't
// displace the warmed transition matrix.
__global__ __launch_bounds__(256, 1)
void backward_kernel(const float* __restrict__ feats,
                     const int*   __restrict__ mask,
                     float*       __restrict__ out) {
    const int b = blockIdx.x;
    const int tid = threadIdx.x;

    // Warm transT into L1 (evict-normal). 16384 f4 / 256 thr = 64 per thread.
    for (int idx = tid; idx < TAGq * TAGq / 4; idx += 256) {
        float4 v;
        asm volatile("ld.global.nc.v4.f32 {%0,%1,%2,%3}, [%4];"
                     : "=f"(v.x), "=f"(v.y), "=f"(v.z), "=f"(v.w)
                     : "l"(((const float4*)g_transT) + idx));
    }
    __syncthreads();

    if (tid >= 32) return;      // chain runs on warp 0 only
    const int lane = tid;

    // lengths = sum(mask[b,:])  (also warms the mask row into L1)
    int len = 0;
    for (int i = lane; i < Tq; i += 32) len += mask[b * Tq + i];
    #pragma unroll
    for (int o = 16; o; o >>= 1) len += __shfl_down_sync(0xffffffffu, len, o);
    len = __shfl_sync(0xffffffffu, len, 0);
    const int last = len - 1;

    const float* hb = g_hist + (size_t)b * Tq * TAGq;
    const int j0 = lane * 4;
    const int j1 = 128 + lane * 4;

    // Pre-touch rows needed by the first chain iteration (i = Tq-2):
    // e row feats[b, Tq-1, :] and hist[b, Tq-2, :].
    touch_cs(feats + ((size_t)b * Tq + (Tq - 1)) * TAGq + lane * 8);
    touch_cs(hb + (size_t)(Tq - 2) * TAGq + lane * 8);

    // path score / pointer: argmax_j last_part[j] + trans[j][STOP]
    int ptr;
    {
        const float4* lp4 = (const float4*)(hb + (size_t)last * TAGq);
        const float4* tc4 = (const float4*)(g_transT + STOP_TAG * TAGq);
        float4 A = lp4[lane], B = lp4[lane + 32];
        float4 C = tc4[lane], D = tc4[lane + 32];
        float v[8] = {A.x + C.x, A.y + C.y, A.z + C.z, A.w + C.w,
                      B.x + D.x, B.y + D.y, B.z + D.z, B.w + D.w};
        float xv = v[0]; int xi = j0;
        #pragma unroll
        for (int k = 1; k < 4; ++k)
            if (v[k] > xv) { xv = v[k]; xi = j0 + k; }
        #pragma unroll
        for (int k = 0; k < 4; ++k)
            if (v[4 + k] > xv) { xv = v[4 + k]; xi = j1 + k; }
        float bv;
        ptr = warp_argmax256(xv, xi, &bv);
        if (lane == 0) out[b] = bv;
    }

    float* dec = out + Bq;
    if (lane == 0) dec[(size_t)b * Tq + (Tq - 1)] = (float)ptr;

    int cur = ptr;
    for (int i = Tq - 2; i >= 0; --i) {
        // Streaming prefetch-touch of rows needed at iteration i-1
        // (index-predictable, independent of cur): feats[b, i, :] and
        // hist[b, i-1, :]. 32 lanes x stride-8 = one touch per 32B sector.
        touch_cs(feats + ((size_t)b * Tq + i) * TAGq + lane * 8);
        if (i >= 1)
            touch_cs(hb + (size_t)(i - 1) * TAGq + lane * 8);

        int nv;
        if (i == last) {
            nv = ptr;
        } else if (mask[b * Tq + i + 1] == 0) {
            nv = 0;
        } else {
            // recompute bp at time i+1, column cur — identical arithmetic
            // to the forward pass: (emit + trans) + part
            const float e =
                __ldg(feats + ((size_t)b * Tq + (i + 1)) * TAGq + cur);
            const float4* h4 = (const float4*)(hb + (size_t)i * TAGq);
            const float4* t4 = (const float4*)(g_transT + (size_t)cur * TAGq);
            float4 H0 = h4[lane], H1 = h4[lane + 32];
            float4 T0 = __ldg(t4 + lane), T1 = __ldg(t4 + lane + 32);
            float v[8] = {(e + T0.x) + H0.x, (e + T0.y) + H0.y,
                          (e + T0.z) + H0.z, (e + T0.w) + H0.w,
                          (e + T1.x) + H1.x, (e + T1.y) + H1.y,
                          (e + T1.z) + H1.z, (e + T1.w) + H1.w};
            float xv = v[0]; int xi = j0;
            #pragma unroll
            for (int k = 1; k < 4; ++k)
                if (v[k] > xv) { xv = v[k]; xi = j0 + k; }
            #pragma unroll
            for (int k = 0; k < 4; ++k)
                if (v[4 + k] > xv) { xv = v[4 + k]; xi = j1 + k; }
            nv = warp_argmax256(xv, xi, nullptr);
        }
        cur = nv;
        if (lane == 0) dec[(size_t)b * Tq + i] = (float)cur;
    }
}

// ---------------------------------------------------------------------------
extern "C" void kernel_launch(void* const* d_in, const int* in_sizes, int n_in,
                              void* d_out, int out_size) {
    const float* feats = (const float*)d_in[0];   // (128,512,256) f32
    const int*   mask  = (const int*)d_in[1];     // (128,512) i32
    const float* trans = (const float*)d_in[2];   // (256,256) f32
    float* out = (float*)d_out;                   // [128 path_score | 128*512 decode]

    transpose_kernel<<<TAGq, TAGq>>>(trans);      // launch #1
    dummy_kernel<<<1, 32>>>();                    // launch #2

    const size_t smem_f =
        (size_t)(TAGq * TSTRIDE4 * 4 + 2 * TAGq) * sizeof(float); // 104448 B
    cudaFuncSetAttribute(forward_kernel,
                         cudaFuncAttributeMaxDynamicSharedMemorySize, (int)smem_f);
    forward_kernel<<<Bq, NTHREADS, smem_f>>>(feats, trans);       // launch #3

    backward_kernel<<<Bq, 256>>>(feats, mask, out);               // launch #4 (ncu)
}